// round 1
// baseline (speedup 1.0000x reference)
#include <cuda_runtime.h>

#define NCONE 8
#define NDIM 24          // 3 * NCONE
#define NITERS 100
#define BATCH 65536
#define POWER_ITERS 400

// ---------------------------------------------------------------------------
// Device globals (scratch; no allocation allowed)
// ---------------------------------------------------------------------------
__device__ float g_A[NDIM * NDIM];   // A = I - step * P   (row k, col j)
__device__ float g_step;

// ---------------------------------------------------------------------------
// Packed f32x2 helpers (Blackwell fma.rn.f32x2 — 2 fp32 FMAs per instruction)
// ---------------------------------------------------------------------------
__device__ __forceinline__ unsigned long long pack2(float a, float b) {
    unsigned long long r;
    asm("mov.b64 %0, {%1, %2};" : "=l"(r) : "f"(a), "f"(b));
    return r;
}
__device__ __forceinline__ void unpack2(unsigned long long v, float& a, float& b) {
    asm("mov.b64 {%0, %1}, %2;" : "=f"(a), "=f"(b) : "l"(v));
}
__device__ __forceinline__ unsigned long long fma2(unsigned long long a,
                                                   unsigned long long b,
                                                   unsigned long long c) {
    unsigned long long d;
    asm("fma.rn.f32x2 %0, %1, %2, %3;" : "=l"(d) : "l"(a), "l"(b), "l"(c));
    return d;
}

// ---------------------------------------------------------------------------
// Prep kernel: power iteration for the top eigenvalue of P (24x24 SPD),
// then A = I - (1/L) * P.   One warp; deterministic (v0 = ones).
// Rayleigh-quotient accuracy ~ (l2/l1)^(2k): k=400 is far past fp32 precision.
// ---------------------------------------------------------------------------
__global__ void prep_kernel(const float* __restrict__ P) {
    __shared__ float Ps[NDIM * NDIM];
    __shared__ float v[NDIM];
    __shared__ float w[NDIM];
    const int t = threadIdx.x;

    for (int i = t; i < NDIM * NDIM; i += 32) Ps[i] = P[i];
    if (t < NDIM) v[t] = 1.0f;
    __syncthreads();

    for (int it = 0; it < POWER_ITERS; it++) {
        float s = 0.0f;
        if (t < NDIM) {
            #pragma unroll
            for (int k = 0; k < NDIM; k++) s += Ps[t * NDIM + k] * v[k];
            w[t] = s;
        }
        __syncthreads();
        float sq = (t < NDIM) ? w[t] * w[t] : 0.0f;
        #pragma unroll
        for (int off = 16; off > 0; off >>= 1)
            sq += __shfl_xor_sync(0xffffffffu, sq, off);
        float rinv = rsqrtf(sq);
        if (t < NDIM) v[t] = w[t] * rinv;
        __syncthreads();
    }

    // Rayleigh quotient: lam = (v^T P v) / (v^T v)
    float s = 0.0f;
    if (t < NDIM) {
        #pragma unroll
        for (int k = 0; k < NDIM; k++) s += Ps[t * NDIM + k] * v[k];
    }
    float num = (t < NDIM) ? v[t] * s : 0.0f;
    float den = (t < NDIM) ? v[t] * v[t] : 0.0f;
    #pragma unroll
    for (int off = 16; off > 0; off >>= 1) {
        num += __shfl_xor_sync(0xffffffffu, num, off);
        den += __shfl_xor_sync(0xffffffffu, den, off);
    }
    const float step = den / num;  // 1 / lambda_max
    if (t == 0) g_step = step;

    for (int i = t; i < NDIM * NDIM; i += 32) {
        int r = i / NDIM, c = i % NDIM;
        g_A[i] = ((r == c) ? 1.0f : 0.0f) - step * Ps[i];
    }
}

// ---------------------------------------------------------------------------
// Main solver: one thread per batch row. l[24] lives in registers for all
// 100 iterations. Matvec done as 288 packed FFMA2 per iteration with A read
// from shared via 16B vector loads (uniform address -> broadcast, no
// conflicts). SOC projection fully branchless (SEL-friendly).
// ---------------------------------------------------------------------------
__global__ void __launch_bounds__(128)
solve_kernel(const float* __restrict__ q, float* __restrict__ out) {
    __shared__ __align__(16) float Ash[NDIM][NDIM];

    const int tid = threadIdx.x;
    for (int i = tid; i < NDIM * NDIM; i += blockDim.x)
        (&Ash[0][0])[i] = g_A[i];
    __syncthreads();

    const float stepv = g_step;
    const int row = blockIdx.x * blockDim.x + tid;

    // b = -step * q[row]   (packed into 12 f32x2 pairs, reused every iter)
    const float4* q4 = reinterpret_cast<const float4*>(q + (size_t)row * NDIM);
    float b[NDIM];
    #pragma unroll
    for (int i = 0; i < 6; i++) {
        float4 v = q4[i];
        b[4 * i + 0] = -stepv * v.x;
        b[4 * i + 1] = -stepv * v.y;
        b[4 * i + 2] = -stepv * v.z;
        b[4 * i + 3] = -stepv * v.w;
    }
    unsigned long long b2[12];
    #pragma unroll
    for (int jp = 0; jp < 12; jp++) b2[jp] = pack2(b[2 * jp], b[2 * jp + 1]);

    float l[NDIM];
    #pragma unroll
    for (int j = 0; j < NDIM; j++) l[j] = 0.0f;

    #pragma unroll 1
    for (int it = 0; it < NITERS; it++) {
        // y = l @ A + b    (y_j = b_j + sum_k l_k * A[k][j])
        unsigned long long acc[12];
        #pragma unroll
        for (int jp = 0; jp < 12; jp++) acc[jp] = b2[jp];

        #pragma unroll
        for (int k = 0; k < NDIM; k++) {
            const unsigned long long lk = pack2(l[k], l[k]);
            const ulonglong2* rp = reinterpret_cast<const ulonglong2*>(&Ash[k][0]);
            #pragma unroll
            for (int m = 0; m < 6; m++) {
                ulonglong2 p = rp[m];
                acc[2 * m + 0] = fma2(lk, p.x, acc[2 * m + 0]);
                acc[2 * m + 1] = fma2(lk, p.y, acc[2 * m + 1]);
            }
        }

        float y[NDIM];
        #pragma unroll
        for (int jp = 0; jp < 12; jp++) unpack2(acc[jp], y[2 * jp], y[2 * jp + 1]);

        // Project onto product of 8 second-order cones:
        //   cone i: t = y[i],  x = (y[8+2i], y[9+2i]),  n = ||x||
        #pragma unroll
        for (int i = 0; i < NCONE; i++) {
            float t  = y[i];
            float x0 = y[NCONE + 2 * i + 0];
            float x1 = y[NCONE + 2 * i + 1];
            float n  = sqrtf(x0 * x0 + x1 * x1);
            float coef = 0.5f * (t + n);
            float sn   = (n > 0.0f) ? n : 1.0f;
            float sc   = coef * __fdividef(1.0f, sn);
            bool inside = (n <= t);
            bool below  = (n <= -t);
            float tn = inside ? t    : (below ? 0.0f : coef);
            float s  = inside ? 1.0f : (below ? 0.0f : sc);
            l[i]                   = tn;
            l[NCONE + 2 * i + 0]   = x0 * s;
            l[NCONE + 2 * i + 1]   = x1 * s;
        }
    }

    float4* o4 = reinterpret_cast<float4*>(out + (size_t)row * NDIM);
    #pragma unroll
    for (int i = 0; i < 6; i++)
        o4[i] = make_float4(l[4 * i + 0], l[4 * i + 1], l[4 * i + 2], l[4 * i + 3]);
}

// ---------------------------------------------------------------------------
// Entry point
// ---------------------------------------------------------------------------
extern "C" void kernel_launch(void* const* d_in, const int* in_sizes, int n_in,
                              void* d_out, int out_size) {
    const float* P = (const float*)d_in[0];   // (1, 24, 24) fp32
    const float* q = (const float*)d_in[1];   // (65536, 24, 1) fp32
    float* out = (float*)d_out;               // (65536, 24) fp32

    prep_kernel<<<1, 32>>>(P);
    solve_kernel<<<BATCH / 128, 128>>>(q, out);
}